// round 9
// baseline (speedup 1.0000x reference)
#include <cuda_runtime.h>

// WaveFunctionDensity: rho[n,m] = sum_pq B[n,m,p] * dm[n,p,q] * B[n,m,q]
//   B[n,m,p] = dx^px * dy^py * dz^pz * exp(-alpha_p * r2[m, center_p])
//
// Shapes: n=16, ms=4096, na=32, np=512.
// CTA = (molecule, 64-sample tile), 256 threads.
//   Phase 1: build basis tile sB[512][64] in smem.
//   Phase 2: register-tiled 16m x 8q quadratic form over the FULL q range,
//            inner product in packed f32x2 (FFMA2) — m-pairs packed so the
//            LDS.128 basis loads are already packed operands.
//            dm streamed via cp.async double-buffered 16x512 chunks.

#define N_MOL   16
#define MS      4096
#define NA      32
#define NP      512
#define M_TILE  64
#define P_CHUNK 16
#define NCHUNK  (NP / P_CHUNK)
#define THREADS 256
#define DV_LD   65

// smem layout (floats):
//   sB   : [NP][M_TILE]          = 32768 floats (131072 B)
//   sD   : 2 x [P_CHUNK][NP]     = 16384 floats ( 65536 B)
//          (phase-1 scratch aliases sD: dvT 96x65, r2 32x64)
//   sExp : 512 f, sCen/sSym : 512 i each, rho : 64 f
#define SMEM_FLOATS (32768 + 16384 + 512 + 512 + 512 + 64)
#define SMEM_BYTES  (SMEM_FLOATS * 4)

typedef unsigned long long u64;

__constant__ int c_pw[20 * 3] = {
    0,0,0,
    1,0,0, 0,1,0, 0,0,1,
    2,0,0, 0,2,0, 0,0,2, 1,1,0, 1,0,1, 0,1,1,
    3,0,0, 0,3,0, 0,0,3, 2,1,0, 2,0,1, 0,2,1,
    1,2,0, 1,0,2, 0,1,2, 1,1,1
};

__device__ __forceinline__ float ipow_small(float x, int e) {
    // x^e for e in {0,1,2,3}; pow(x,0)==1 for any x (matches XLA semantics)
    float r = (e > 0 ? x : 1.0f);
    r *= (e > 1 ? x : 1.0f);
    r *= (e > 2 ? x : 1.0f);
    return r;
}

// packed f32x2 fma: returns a*b + c per 32-bit lane (rn rounding, same as fmaf)
__device__ __forceinline__ u64 ffma2(u64 a, u64 b, u64 c) {
    u64 d;
    asm("fma.rn.f32x2 %0, %1, %2, %3;" : "=l"(d) : "l"(a), "l"(b), "l"(c));
    return d;
}
// duplicate one fp32 into both halves of an f32x2
__device__ __forceinline__ u64 dup2(float x) {
    u64 d; unsigned r = __float_as_uint(x);
    asm("mov.b64 %0, {%1, %2};" : "=l"(d) : "r"(r), "r"(r));
    return d;
}
__device__ __forceinline__ void unpack2(u64 v, float& lo, float& hi) {
    unsigned a, b;
    asm("mov.b64 {%0, %1}, %2;" : "=r"(a), "=r"(b) : "l"(v));
    lo = __uint_as_float(a); hi = __uint_as_float(b);
}

__device__ __forceinline__ void cp_async16(float* smem_dst, const float* gmem_src) {
    unsigned s = (unsigned)__cvta_generic_to_shared(smem_dst);
    asm volatile("cp.async.cg.shared.global [%0], [%1], 16;\n" :: "r"(s), "l"(gmem_src));
}
__device__ __forceinline__ void cp_async_commit() {
    asm volatile("cp.async.commit_group;\n" ::: "memory");
}
__device__ __forceinline__ void cp_async_wait1() {
    asm volatile("cp.async.wait_group 1;\n" ::: "memory");
}
__device__ __forceinline__ void cp_async_wait0() {
    asm volatile("cp.async.wait_group 0;\n" ::: "memory");
}

__global__ __launch_bounds__(THREADS, 1)
void wfn_density_kernel(const float* __restrict__ dv,
                        const int*   __restrict__ centers,
                        const float* __restrict__ exps,
                        const int*   __restrict__ syms,
                        const float* __restrict__ dm,
                        float*       __restrict__ out) {
    extern __shared__ float smem[];
    float* sB   = smem;                         // 32768 floats
    float* sD0  = smem + 32768;                 // 8192 floats (16x512)
    float* sD1  = sD0 + P_CHUNK * NP;           // 8192 floats
    float* sExp = smem + 32768 + 16384;         // 512
    int*   sCen = (int*)(sExp + 512);
    int*   sSym = sCen + 512;
    float* rhoS = (float*)(sSym + 512);         // 64

    // phase-1 scratch spans sD0 (+ start of sD1)
    float* dvT = sD0;                  // [96][DV_LD]
    float* r2s = sD0 + 96 * DV_LD;     // [32][64]

    const int tid = threadIdx.x;
    const int n   = blockIdx.y;
    const int m0  = blockIdx.x * M_TILE;

    // ---- per-primitive params ----
    for (int i = tid; i < NP; i += THREADS) {
        sExp[i] = exps[n * NP + i];
        sCen[i] = centers[n * NP + i];
        sSym[i] = syms[n * NP + i];
    }
    if (tid < M_TILE) rhoS[tid] = 0.0f;

    // ---- dv tile, transposed ----
    const float* dvsrc = dv + ((size_t)n * MS + m0) * (NA * 3);
    for (int L = tid; L < M_TILE * NA * 3; L += THREADS) {
        int mm = L / (NA * 3);
        int t  = L % (NA * 3);
        dvT[t * DV_LD + mm] = dvsrc[L];
    }
    __syncthreads();

    // ---- r2 per (atom, sample) ----
    for (int idx = tid; idx < NA * M_TILE; idx += THREADS) {
        int a = idx >> 6, mm = idx & 63;
        float x = dvT[(a * 3 + 0) * DV_LD + mm];
        float y = dvT[(a * 3 + 1) * DV_LD + mm];
        float z = dvT[(a * 3 + 2) * DV_LD + mm];
        r2s[a * 64 + mm] = x * x + y * y + z * z;
    }
    __syncthreads();

    // ---- basis tile sB[p][mm] ----
    for (int e = tid; e < NP * M_TILE; e += THREADS) {
        int p  = e >> 6;
        int mm = e & 63;
        int c  = sCen[p];
        int cc = max(c, 0);
        float alpha = sExp[p];
        int s  = sSym[p];
        int px = c_pw[s * 3 + 0], py = c_pw[s * 3 + 1], pz = c_pw[s * 3 + 2];
        float x  = dvT[(cc * 3 + 0) * DV_LD + mm];
        float y  = dvT[(cc * 3 + 1) * DV_LD + mm];
        float z  = dvT[(cc * 3 + 2) * DV_LD + mm];
        float r2 = r2s[cc * 64 + mm];
        float ang = ipow_small(x, px) * ipow_small(y, py) * ipow_small(z, pz);
        float b = ang * __expf(-alpha * r2);
        sB[p * M_TILE + mm] = (c >= 0) ? b : 0.0f;
    }
    __syncthreads();   // phase-1 reads of sD-aliased scratch complete

    // ---- phase 2: acc[m, q] = sum_p B[m,p] D[p,q]  (16m x 8q per thread,
    //      m packed in pairs -> 8 x 8 f32x2 accumulators) ----
    const float* Dg = dm + (size_t)n * NP * NP;
    const int tm = tid & 3;     // m-group: m = tm*16 + i, i in 0..15
    const int tq = tid >> 2;    // q-group: q = tq*8 + j, j in 0..7
    float* bufs[2] = { sD0, sD1 };

    u64 acc2[8][8];
    #pragma unroll
    for (int i = 0; i < 8; ++i)
        #pragma unroll
        for (int j = 0; j < 8; ++j) acc2[i][j] = 0ull;

    // prologue: chunk 0 (contiguous 16x512 region)
    {
        const float* src = Dg;
        #pragma unroll
        for (int v = tid; v < P_CHUNK * NP / 4; v += THREADS)
            cp_async16(&bufs[0][v * 4], &src[v * 4]);
        cp_async_commit();
    }

    for (int ic = 0; ic < NCHUNK; ++ic) {
        if (ic + 1 < NCHUNK) {
            float* b = bufs[(ic + 1) & 1];
            const float* src = Dg + (size_t)(ic + 1) * P_CHUNK * NP;
            #pragma unroll
            for (int v = tid; v < P_CHUNK * NP / 4; v += THREADS)
                cp_async16(&b[v * 4], &src[v * 4]);
            cp_async_commit();
            cp_async_wait1();   // chunk ic resident
        } else {
            cp_async_wait0();
        }
        __syncthreads();

        const float* sD = bufs[ic & 1];
        const int pc = ic * P_CHUNK;
        #pragma unroll 2
        for (int pp = 0; pp < P_CHUNK; ++pp) {
            // basis m-pairs: LDS.128 reinterpreted as two packed f32x2 (zero-cost)
            const float* brow = &sB[(pc + pp) * M_TILE + tm * 16];
            ulonglong2 B0 = *(const ulonglong2*)&brow[0];
            ulonglong2 B1 = *(const ulonglong2*)&brow[4];
            ulonglong2 B2 = *(const ulonglong2*)&brow[8];
            ulonglong2 B3 = *(const ulonglong2*)&brow[12];
            u64 bb2[8] = { B0.x, B0.y, B1.x, B1.y, B2.x, B2.y, B3.x, B3.y };

            const float* drow = &sD[pp * NP + tq * 8];
            float4 d0 = *(const float4*)&drow[0];
            float4 d1 = *(const float4*)&drow[4];
            u64 dd2[8] = { dup2(d0.x), dup2(d0.y), dup2(d0.z), dup2(d0.w),
                           dup2(d1.x), dup2(d1.y), dup2(d1.z), dup2(d1.w) };

            #pragma unroll
            for (int i = 0; i < 8; ++i)
                #pragma unroll
                for (int j = 0; j < 8; ++j)
                    acc2[i][j] = ffma2(bb2[i], dd2[j], acc2[i][j]);
        }
        __syncthreads();   // readers done before this buffer is refilled
    }

    // ---- epilogue: part[i] = sum_j acc[i][j] * B[q_j, m_i], packed ----
    u64 part2[8];
    #pragma unroll
    for (int i = 0; i < 8; ++i) part2[i] = 0ull;
    #pragma unroll
    for (int j = 0; j < 8; ++j) {
        int q = tq * 8 + j;
        const float* col = &sB[q * M_TILE + tm * 16];
        ulonglong2 C0 = *(const ulonglong2*)&col[0];
        ulonglong2 C1 = *(const ulonglong2*)&col[4];
        ulonglong2 C2 = *(const ulonglong2*)&col[8];
        ulonglong2 C3 = *(const ulonglong2*)&col[12];
        u64 cc2[8] = { C0.x, C0.y, C1.x, C1.y, C2.x, C2.y, C3.x, C3.y };
        #pragma unroll
        for (int i = 0; i < 8; ++i)
            part2[i] = ffma2(acc2[i][j], cc2[i], part2[i]);
    }
    float part[16];
    #pragma unroll
    for (int i = 0; i < 8; ++i)
        unpack2(part2[i], part[2 * i], part[2 * i + 1]);

    // reduce across the 8 lanes in this warp that share tm (lane bits 2,3,4)
    #pragma unroll
    for (int i = 0; i < 16; ++i) {
        part[i] += __shfl_xor_sync(0xFFFFFFFFu, part[i], 4);
        part[i] += __shfl_xor_sync(0xFFFFFFFFu, part[i], 8);
        part[i] += __shfl_xor_sync(0xFFFFFFFFu, part[i], 16);
    }
    if (((tid >> 2) & 7) == 0) {   // one lane per tm-group per warp
        #pragma unroll
        for (int i = 0; i < 16; ++i)
            atomicAdd(&rhoS[tm * 16 + i], part[i]);
    }

    __syncthreads();
    if (tid < M_TILE)
        out[(size_t)n * MS + m0 + tid] = rhoS[tid];
}

extern "C" void kernel_launch(void* const* d_in, const int* in_sizes, int n_in,
                              void* d_out, int out_size) {
    const float* dv      = (const float*)d_in[0];
    const int*   centers = (const int*)  d_in[1];
    const float* exps    = (const float*)d_in[2];
    const int*   syms    = (const int*)  d_in[3];
    const float* dm      = (const float*)d_in[4];
    float* out = (float*)d_out;

    cudaFuncSetAttribute(wfn_density_kernel,
                         cudaFuncAttributeMaxDynamicSharedMemorySize, SMEM_BYTES);

    dim3 grid(MS / M_TILE, N_MOL);
    wfn_density_kernel<<<grid, THREADS, SMEM_BYTES>>>(dv, centers, exps, syms, dm, out);
}

// round 10
// speedup vs baseline: 1.2359x; 1.2359x over previous
#include <cuda_runtime.h>

// WaveFunctionDensity: rho[n,m] = sum_pq B[n,m,p] * dm[n,p,q] * B[n,m,q]
// Symmetrized block-triangular form:
//   U[p,q] = (D[p,q]+D[q,p]) * w,  w = 1 if ptile<qtile, 0.5 if ==, (0 if >)
//   rho[m] = sum_q b_q * sum_{ptile<=qtile} U[p,q] b_p      (ptile = p>>6)
//
// Kernel 1: build U into __device__ scratch (only ptile<=qtile blocks).
// Kernel 2: R7 champion structure (256 thr, 16m x 8q full-q register tile,
//   cp.async double-buffered 16x512 chunks) + warp-level chunk skipping:
//   warp w owns q-tile (w<4 ? w : 11-w), computes chunk ic iff ic>>2 <= tile.

#define N_MOL   16
#define MS      4096
#define NA      32
#define NP      512
#define M_TILE  64
#define P_CHUNK 16
#define NCHUNK  (NP / P_CHUNK)
#define THREADS 256
#define DV_LD   65

#define SMEM_FLOATS (32768 + 16384 + 512 + 512 + 512 + 64)
#define SMEM_BYTES  (SMEM_FLOATS * 4)

// symmetrized, block-weighted density matrix (zero-init; P>Q blocks never
// written and never consumed -> deterministic)
__device__ float g_U[(size_t)N_MOL * NP * NP];

__constant__ int c_pw[20 * 3] = {
    0,0,0,
    1,0,0, 0,1,0, 0,0,1,
    2,0,0, 0,2,0, 0,0,2, 1,1,0, 1,0,1, 0,1,1,
    3,0,0, 0,3,0, 0,0,3, 2,1,0, 2,0,1, 0,2,1,
    1,2,0, 1,0,2, 0,1,2, 1,1,1
};

__device__ __forceinline__ float ipow_small(float x, int e) {
    // x^e for e in {0,1,2,3}; pow(x,0)==1 for any x (matches XLA semantics)
    float r = (e > 0 ? x : 1.0f);
    r *= (e > 1 ? x : 1.0f);
    r *= (e > 2 ? x : 1.0f);
    return r;
}

__device__ __forceinline__ void cp_async16(float* smem_dst, const float* gmem_src) {
    unsigned s = (unsigned)__cvta_generic_to_shared(smem_dst);
    asm volatile("cp.async.cg.shared.global [%0], [%1], 16;\n" :: "r"(s), "l"(gmem_src));
}
__device__ __forceinline__ void cp_async_commit() {
    asm volatile("cp.async.commit_group;\n" ::: "memory");
}
__device__ __forceinline__ void cp_async_wait1() {
    asm volatile("cp.async.wait_group 1;\n" ::: "memory");
}
__device__ __forceinline__ void cp_async_wait0() {
    asm volatile("cp.async.wait_group 0;\n" ::: "memory");
}

// ---- kernel 1: U = (D + D^T) with block-triangular weights ----
__global__ void build_U_kernel(const float* __restrict__ dm) {
    __shared__ float tA[32][33];
    __shared__ float tB[32][33];
    const int n  = blockIdx.z;
    const int bp = blockIdx.y * 32;
    const int bq = blockIdx.x * 32;
    const int ptile = bp >> 6, qtile = bq >> 6;
    if (ptile > qtile) return;                 // unused region stays zero

    const float* D = dm + (size_t)n * NP * NP;
    const int tx = threadIdx.x, ty0 = threadIdx.y;   // block (32, 8)
    for (int r = ty0; r < 32; r += 8) {
        tA[r][tx] = D[(size_t)(bp + r) * NP + bq + tx];
        tB[r][tx] = D[(size_t)(bq + r) * NP + bp + tx];
    }
    __syncthreads();

    const float w = (ptile == qtile) ? 0.5f : 1.0f;
    float* U = g_U + (size_t)n * NP * NP;
    for (int r = ty0; r < 32; r += 8)
        U[(size_t)(bp + r) * NP + bq + tx] = (tA[r][tx] + tB[tx][r]) * w;
}

// ---- kernel 2: fused basis + triangular quadratic form ----
__global__ __launch_bounds__(THREADS, 1)
void wfn_density_kernel(const float* __restrict__ dv,
                        const int*   __restrict__ centers,
                        const float* __restrict__ exps,
                        const int*   __restrict__ syms,
                        float*       __restrict__ out) {
    extern __shared__ float smem[];
    float* sB   = smem;                         // 32768 floats
    float* sD0  = smem + 32768;                 // 8192 floats (16x512)
    float* sD1  = sD0 + P_CHUNK * NP;           // 8192 floats
    float* sExp = smem + 32768 + 16384;         // 512
    int*   sCen = (int*)(sExp + 512);
    int*   sSym = sCen + 512;
    float* rhoS = (float*)(sSym + 512);         // 64

    // phase-1 scratch aliases the sD buffers
    float* dvT = sD0;                  // [96][DV_LD]
    float* r2s = sD0 + 96 * DV_LD;     // [32][64]

    const int tid = threadIdx.x;
    const int n   = blockIdx.y;
    const int m0  = blockIdx.x * M_TILE;

    // ---- per-primitive params ----
    for (int i = tid; i < NP; i += THREADS) {
        sExp[i] = exps[n * NP + i];
        sCen[i] = centers[n * NP + i];
        sSym[i] = syms[n * NP + i];
    }
    if (tid < M_TILE) rhoS[tid] = 0.0f;

    // ---- dv tile, transposed ----
    const float* dvsrc = dv + ((size_t)n * MS + m0) * (NA * 3);
    for (int L = tid; L < M_TILE * NA * 3; L += THREADS) {
        int mm = L / (NA * 3);
        int t  = L % (NA * 3);
        dvT[t * DV_LD + mm] = dvsrc[L];
    }
    __syncthreads();

    // ---- r2 per (atom, sample) ----
    for (int idx = tid; idx < NA * M_TILE; idx += THREADS) {
        int a = idx >> 6, mm = idx & 63;
        float x = dvT[(a * 3 + 0) * DV_LD + mm];
        float y = dvT[(a * 3 + 1) * DV_LD + mm];
        float z = dvT[(a * 3 + 2) * DV_LD + mm];
        r2s[a * 64 + mm] = x * x + y * y + z * z;
    }
    __syncthreads();

    // ---- basis tile sB[p][mm] ----
    for (int e = tid; e < NP * M_TILE; e += THREADS) {
        int p  = e >> 6;
        int mm = e & 63;
        int c  = sCen[p];
        int cc = max(c, 0);
        float alpha = sExp[p];
        int s  = sSym[p];
        int px = c_pw[s * 3 + 0], py = c_pw[s * 3 + 1], pz = c_pw[s * 3 + 2];
        float x  = dvT[(cc * 3 + 0) * DV_LD + mm];
        float y  = dvT[(cc * 3 + 1) * DV_LD + mm];
        float z  = dvT[(cc * 3 + 2) * DV_LD + mm];
        float r2 = r2s[cc * 64 + mm];
        float ang = ipow_small(x, px) * ipow_small(y, py) * ipow_small(z, pz);
        float b = ang * __expf(-alpha * r2);
        sB[p * M_TILE + mm] = (c >= 0) ? b : 0.0f;
    }
    __syncthreads();   // phase-1 reads of sD-aliased scratch complete

    // ---- phase 2: acc[m,q] = sum_{ptile<=qtile} U[p,q] b[m,p] ----
    // Warp w owns 64-wide q-tile (w<4 ? w : 11-w) so each SMSP (w%4) gets a
    // balanced complementary pair; chunk ic is computed iff (ic>>2) <= qtile.
    const float* Ug = g_U + (size_t)n * NP * NP;
    const int warp  = tid >> 5;
    const int qtile = (warp < 4) ? warp : 11 - warp;
    const int tm    = tid & 3;          // m-group: m = tm*16 + i, i in 0..15
    const int tqin  = (tid >> 2) & 7;   // q-group within warp, j in 0..7
    const int q0    = qtile * 64 + tqin * 8;
    float* bufs[2] = { sD0, sD1 };

    float acc[16][8];
    #pragma unroll
    for (int i = 0; i < 16; ++i)
        #pragma unroll
        for (int j = 0; j < 8; ++j) acc[i][j] = 0.0f;

    // prologue: chunk 0 (contiguous 16x512 region)
    {
        const float* src = Ug;
        #pragma unroll
        for (int v = tid; v < P_CHUNK * NP / 4; v += THREADS)
            cp_async16(&bufs[0][v * 4], &src[v * 4]);
        cp_async_commit();
    }

    for (int ic = 0; ic < NCHUNK; ++ic) {
        if (ic + 1 < NCHUNK) {
            float* b = bufs[(ic + 1) & 1];
            const float* src = Ug + (size_t)(ic + 1) * P_CHUNK * NP;
            #pragma unroll
            for (int v = tid; v < P_CHUNK * NP / 4; v += THREADS)
                cp_async16(&b[v * 4], &src[v * 4]);
            cp_async_commit();
            cp_async_wait1();   // chunk ic resident
        } else {
            cp_async_wait0();
        }
        __syncthreads();

        if ((ic >> 2) <= qtile) {      // warp-uniform triangular skip
            const float* sD = bufs[ic & 1];
            const int pc = ic * P_CHUNK;
            #pragma unroll 2
            for (int pp = 0; pp < P_CHUNK; ++pp) {
                const float* brow = &sB[(pc + pp) * M_TILE + tm * 16];
                float4 b0 = *(const float4*)&brow[0];
                float4 b1 = *(const float4*)&brow[4];
                float4 b2 = *(const float4*)&brow[8];
                float4 b3 = *(const float4*)&brow[12];
                const float* drow = &sD[pp * NP + q0];
                float4 d0 = *(const float4*)&drow[0];
                float4 d1 = *(const float4*)&drow[4];
                float bb[16] = {b0.x, b0.y, b0.z, b0.w, b1.x, b1.y, b1.z, b1.w,
                                b2.x, b2.y, b2.z, b2.w, b3.x, b3.y, b3.z, b3.w};
                float dd[8]  = {d0.x, d0.y, d0.z, d0.w, d1.x, d1.y, d1.z, d1.w};
                #pragma unroll
                for (int i = 0; i < 16; ++i)
                    #pragma unroll
                    for (int j = 0; j < 8; ++j)
                        acc[i][j] = fmaf(bb[i], dd[j], acc[i][j]);
            }
        }
        __syncthreads();   // readers done before this buffer is refilled
    }

    // ---- epilogue: part[i] = sum_j acc[i][j] * B[q_j, m_i] ----
    float part[16];
    #pragma unroll
    for (int i = 0; i < 16; ++i) part[i] = 0.0f;
    #pragma unroll
    for (int j = 0; j < 8; ++j) {
        int q = q0 + j;
        const float* col = &sB[q * M_TILE + tm * 16];
        float4 c0 = *(const float4*)&col[0];
        float4 c1 = *(const float4*)&col[4];
        float4 c2 = *(const float4*)&col[8];
        float4 c3 = *(const float4*)&col[12];
        float cc[16] = {c0.x, c0.y, c0.z, c0.w, c1.x, c1.y, c1.z, c1.w,
                        c2.x, c2.y, c2.z, c2.w, c3.x, c3.y, c3.z, c3.w};
        #pragma unroll
        for (int i = 0; i < 16; ++i)
            part[i] = fmaf(acc[i][j], cc[i], part[i]);
    }
    // reduce across the 8 lanes in this warp that share tm (lane bits 2,3,4)
    #pragma unroll
    for (int i = 0; i < 16; ++i) {
        part[i] += __shfl_xor_sync(0xFFFFFFFFu, part[i], 4);
        part[i] += __shfl_xor_sync(0xFFFFFFFFu, part[i], 8);
        part[i] += __shfl_xor_sync(0xFFFFFFFFu, part[i], 16);
    }
    if (tqin == 0) {   // one lane per tm-group per warp
        #pragma unroll
        for (int i = 0; i < 16; ++i)
            atomicAdd(&rhoS[tm * 16 + i], part[i]);
    }

    __syncthreads();
    if (tid < M_TILE)
        out[(size_t)n * MS + m0 + tid] = rhoS[tid];
}

extern "C" void kernel_launch(void* const* d_in, const int* in_sizes, int n_in,
                              void* d_out, int out_size) {
    const float* dv      = (const float*)d_in[0];
    const int*   centers = (const int*)  d_in[1];
    const float* exps    = (const float*)d_in[2];
    const int*   syms    = (const int*)  d_in[3];
    const float* dm      = (const float*)d_in[4];
    float* out = (float*)d_out;

    cudaFuncSetAttribute(wfn_density_kernel,
                         cudaFuncAttributeMaxDynamicSharedMemorySize, SMEM_BYTES);

    // 1) symmetrize + weight the density matrix
    dim3 ug(NP / 32, NP / 32, N_MOL);
    build_U_kernel<<<ug, dim3(32, 8)>>>(dm);

    // 2) fused density evaluation
    dim3 grid(MS / M_TILE, N_MOL);
    wfn_density_kernel<<<grid, THREADS, SMEM_BYTES>>>(dv, centers, exps, syms, out);
}

// round 11
// speedup vs baseline: 1.2825x; 1.0377x over previous
#include <cuda_runtime.h>

// WaveFunctionDensity: rho[n,m] = sum_pq B[n,m,p] * dm[n,p,q] * B[n,m,q]
// Symmetrized block-triangular form:
//   U[p,q] = (D[p,q]+D[q,p]) * w,  w = 1 if ptile<qtile, 0.5 if ==, (0 if >)
//   rho[m] = sum_q b_q * sum_{ptile<=qtile} U[p,q] b_p      (ptile = p>>6)
//
// Kernel 1: build U into __device__ scratch (only ptile<=qtile blocks).
// Kernel 2: fused basis + quadratic form. Warps FREE-RUN over their own
//   triangular p-range reading U straight from L2 (no smem staging, no
//   mainloop barriers); distance-2 register prefetch hides L2 latency.
//   Warp w owns q-tile (w<4 ? w : 11-w) -> complementary pair per SMSP,
//   perfectly balanced 36 chunk-units per SMSP.

#define N_MOL   16
#define MS      4096
#define NA      32
#define NP      512
#define M_TILE  64
#define THREADS 256
#define DV_LD   65

// smem (floats): sB 32768 | scratch dvT 96*65 + r2 32*64 = 8288 | params 1536 | rho 64
#define SCRATCH_FLOATS (96 * DV_LD + 32 * 64)
#define SMEM_FLOATS (32768 + SCRATCH_FLOATS + 512 + 512 + 512 + 64)
#define SMEM_BYTES  (SMEM_FLOATS * 4)

// symmetrized, block-weighted density matrix (zero-init; P>Q blocks never
// written and never consumed -> deterministic)
__device__ float g_U[(size_t)N_MOL * NP * NP];

__constant__ int c_pw[20 * 3] = {
    0,0,0,
    1,0,0, 0,1,0, 0,0,1,
    2,0,0, 0,2,0, 0,0,2, 1,1,0, 1,0,1, 0,1,1,
    3,0,0, 0,3,0, 0,0,3, 2,1,0, 2,0,1, 0,2,1,
    1,2,0, 1,0,2, 0,1,2, 1,1,1
};

__device__ __forceinline__ float ipow_small(float x, int e) {
    // x^e for e in {0,1,2,3}; pow(x,0)==1 for any x (matches XLA semantics)
    float r = (e > 0 ? x : 1.0f);
    r *= (e > 1 ? x : 1.0f);
    r *= (e > 2 ? x : 1.0f);
    return r;
}

// ---- kernel 1: U = (D + D^T) with block-triangular weights ----
__global__ void build_U_kernel(const float* __restrict__ dm) {
    __shared__ float tA[32][33];
    __shared__ float tB[32][33];
    const int n  = blockIdx.z;
    const int bp = blockIdx.y * 32;
    const int bq = blockIdx.x * 32;
    const int ptile = bp >> 6, qtile = bq >> 6;
    if (ptile > qtile) return;                 // unused region stays zero

    const float* D = dm + (size_t)n * NP * NP;
    const int tx = threadIdx.x, ty0 = threadIdx.y;   // block (32, 8)
    for (int r = ty0; r < 32; r += 8) {
        tA[r][tx] = D[(size_t)(bp + r) * NP + bq + tx];
        tB[r][tx] = D[(size_t)(bq + r) * NP + bp + tx];
    }
    __syncthreads();

    const float w = (ptile == qtile) ? 0.5f : 1.0f;
    float* U = g_U + (size_t)n * NP * NP;
    for (int r = ty0; r < 32; r += 8)
        U[(size_t)(bp + r) * NP + bq + tx] = (tA[r][tx] + tB[tx][r]) * w;
}

// ---- kernel 2: fused basis + free-running triangular quadratic form ----
__global__ __launch_bounds__(THREADS, 1)
void wfn_density_kernel(const float* __restrict__ dv,
                        const int*   __restrict__ centers,
                        const float* __restrict__ exps,
                        const int*   __restrict__ syms,
                        float*       __restrict__ out) {
    extern __shared__ float smem[];
    float* sB   = smem;                          // 32768 floats
    float* dvT  = smem + 32768;                  // [96][DV_LD]
    float* r2s  = dvT + 96 * DV_LD;              // [32][64]
    float* sExp = smem + 32768 + SCRATCH_FLOATS; // 512
    int*   sCen = (int*)(sExp + 512);
    int*   sSym = sCen + 512;
    float* rhoS = (float*)(sSym + 512);          // 64

    const int tid = threadIdx.x;
    const int n   = blockIdx.y;
    const int m0  = blockIdx.x * M_TILE;

    // ---- per-primitive params ----
    for (int i = tid; i < NP; i += THREADS) {
        sExp[i] = exps[n * NP + i];
        sCen[i] = centers[n * NP + i];
        sSym[i] = syms[n * NP + i];
    }
    if (tid < M_TILE) rhoS[tid] = 0.0f;

    // ---- dv tile, transposed ----
    const float* dvsrc = dv + ((size_t)n * MS + m0) * (NA * 3);
    for (int L = tid; L < M_TILE * NA * 3; L += THREADS) {
        int mm = L / (NA * 3);
        int t  = L % (NA * 3);
        dvT[t * DV_LD + mm] = dvsrc[L];
    }
    __syncthreads();

    // ---- r2 per (atom, sample) ----
    for (int idx = tid; idx < NA * M_TILE; idx += THREADS) {
        int a = idx >> 6, mm = idx & 63;
        float x = dvT[(a * 3 + 0) * DV_LD + mm];
        float y = dvT[(a * 3 + 1) * DV_LD + mm];
        float z = dvT[(a * 3 + 2) * DV_LD + mm];
        r2s[a * 64 + mm] = x * x + y * y + z * z;
    }
    __syncthreads();

    // ---- basis tile sB[p][mm] ----
    for (int e = tid; e < NP * M_TILE; e += THREADS) {
        int p  = e >> 6;
        int mm = e & 63;
        int c  = sCen[p];
        int cc = max(c, 0);
        float alpha = sExp[p];
        int s  = sSym[p];
        int px = c_pw[s * 3 + 0], py = c_pw[s * 3 + 1], pz = c_pw[s * 3 + 2];
        float x  = dvT[(cc * 3 + 0) * DV_LD + mm];
        float y  = dvT[(cc * 3 + 1) * DV_LD + mm];
        float z  = dvT[(cc * 3 + 2) * DV_LD + mm];
        float r2 = r2s[cc * 64 + mm];
        float ang = ipow_small(x, px) * ipow_small(y, py) * ipow_small(z, pz);
        float b = ang * __expf(-alpha * r2);
        sB[p * M_TILE + mm] = (c >= 0) ? b : 0.0f;
    }
    __syncthreads();   // sB complete; warps free-run from here

    // ---- phase 2: acc[m,q] = sum_{p < (qtile+1)*64} U[p,q] b[m,p] ----
    const float* Ug = g_U + (size_t)n * NP * NP;
    const int warp  = tid >> 5;
    const int qtile = (warp < 4) ? warp : 11 - warp;
    const int tm    = tid & 3;          // m-group: m = tm*16 + i, i in 0..15
    const int tqin  = (tid >> 2) & 7;   // q-group within warp, j in 0..7
    const int q0    = qtile * 64 + tqin * 8;
    const int pmax  = (qtile + 1) * 64;

    float acc[16][8];
    #pragma unroll
    for (int i = 0; i < 16; ++i)
        #pragma unroll
        for (int j = 0; j < 8; ++j) acc[i][j] = 0.0f;

    const float4* Uq = (const float4*)(Ug + q0);   // row p: Uq[p*128], Uq[p*128+1]
    // distance-2 software pipeline over p (process pairs, prefetch next pair)
    float4 uA0 = __ldg(&Uq[0]),   uA1 = __ldg(&Uq[1]);
    float4 uB0 = __ldg(&Uq[128]), uB1 = __ldg(&Uq[129]);

    for (int p = 0; p < pmax; p += 2) {
        float4 c0 = uA0, c1 = uA1, e0 = uB0, e1 = uB1;
        if (p + 3 < pmax) {
            uA0 = __ldg(&Uq[(p + 2) * 128]);
            uA1 = __ldg(&Uq[(p + 2) * 128 + 1]);
            uB0 = __ldg(&Uq[(p + 3) * 128]);
            uB1 = __ldg(&Uq[(p + 3) * 128 + 1]);
        }

        // p
        {
            const float* brow = &sB[p * M_TILE + tm * 16];
            float4 b0 = *(const float4*)&brow[0];
            float4 b1 = *(const float4*)&brow[4];
            float4 b2 = *(const float4*)&brow[8];
            float4 b3 = *(const float4*)&brow[12];
            float bb[16] = {b0.x, b0.y, b0.z, b0.w, b1.x, b1.y, b1.z, b1.w,
                            b2.x, b2.y, b2.z, b2.w, b3.x, b3.y, b3.z, b3.w};
            float dd[8]  = {c0.x, c0.y, c0.z, c0.w, c1.x, c1.y, c1.z, c1.w};
            #pragma unroll
            for (int i = 0; i < 16; ++i)
                #pragma unroll
                for (int j = 0; j < 8; ++j)
                    acc[i][j] = fmaf(bb[i], dd[j], acc[i][j]);
        }
        // p + 1
        {
            const float* brow = &sB[(p + 1) * M_TILE + tm * 16];
            float4 b0 = *(const float4*)&brow[0];
            float4 b1 = *(const float4*)&brow[4];
            float4 b2 = *(const float4*)&brow[8];
            float4 b3 = *(const float4*)&brow[12];
            float bb[16] = {b0.x, b0.y, b0.z, b0.w, b1.x, b1.y, b1.z, b1.w,
                            b2.x, b2.y, b2.z, b2.w, b3.x, b3.y, b3.z, b3.w};
            float dd[8]  = {e0.x, e0.y, e0.z, e0.w, e1.x, e1.y, e1.z, e1.w};
            #pragma unroll
            for (int i = 0; i < 16; ++i)
                #pragma unroll
                for (int j = 0; j < 8; ++j)
                    acc[i][j] = fmaf(bb[i], dd[j], acc[i][j]);
        }
    }

    // ---- epilogue: part[i] = sum_j acc[i][j] * B[q_j, m_i] ----
    float part[16];
    #pragma unroll
    for (int i = 0; i < 16; ++i) part[i] = 0.0f;
    #pragma unroll
    for (int j = 0; j < 8; ++j) {
        int q = q0 + j;
        const float* col = &sB[q * M_TILE + tm * 16];
        float4 c0 = *(const float4*)&col[0];
        float4 c1 = *(const float4*)&col[4];
        float4 c2 = *(const float4*)&col[8];
        float4 c3 = *(const float4*)&col[12];
        float cc[16] = {c0.x, c0.y, c0.z, c0.w, c1.x, c1.y, c1.z, c1.w,
                        c2.x, c2.y, c2.z, c2.w, c3.x, c3.y, c3.z, c3.w};
        #pragma unroll
        for (int i = 0; i < 16; ++i)
            part[i] = fmaf(acc[i][j], cc[i], part[i]);
    }
    // reduce across the 8 lanes in this warp that share tm (lane bits 2,3,4)
    #pragma unroll
    for (int i = 0; i < 16; ++i) {
        part[i] += __shfl_xor_sync(0xFFFFFFFFu, part[i], 4);
        part[i] += __shfl_xor_sync(0xFFFFFFFFu, part[i], 8);
        part[i] += __shfl_xor_sync(0xFFFFFFFFu, part[i], 16);
    }
    if (tqin == 0) {   // one lane per tm-group per warp
        #pragma unroll
        for (int i = 0; i < 16; ++i)
            atomicAdd(&rhoS[tm * 16 + i], part[i]);
    }

    __syncthreads();
    if (tid < M_TILE)
        out[(size_t)n * MS + m0 + tid] = rhoS[tid];
}

extern "C" void kernel_launch(void* const* d_in, const int* in_sizes, int n_in,
                              void* d_out, int out_size) {
    const float* dv      = (const float*)d_in[0];
    const int*   centers = (const int*)  d_in[1];
    const float* exps    = (const float*)d_in[2];
    const int*   syms    = (const int*)  d_in[3];
    const float* dm      = (const float*)d_in[4];
    float* out = (float*)d_out;

    cudaFuncSetAttribute(wfn_density_kernel,
                         cudaFuncAttributeMaxDynamicSharedMemorySize, SMEM_BYTES);

    // 1) symmetrize + weight the density matrix
    dim3 ug(NP / 32, NP / 32, N_MOL);
    build_U_kernel<<<ug, dim3(32, 8)>>>(dm);

    // 2) fused density evaluation
    dim3 grid(MS / M_TILE, N_MOL);
    wfn_density_kernel<<<grid, THREADS, SMEM_BYTES>>>(dv, centers, exps, syms, out);
}

// round 12
// speedup vs baseline: 1.5026x; 1.1716x over previous
#include <cuda_runtime.h>

// WaveFunctionDensity: rho[n,m] = sum_pq B[n,m,p] * dm[n,p,q] * B[n,m,q]
// Symmetrized block-triangular form:
//   U[p,q] = (D[p,q]+D[q,p]) * w,  w = 1 if ptile<qtile, 0.5 if ==, (0 if >)
//   rho[m] = sum_q b_q * sum_{ptile<=qtile} U[p,q] b_p      (ptile = p>>6)
//
// Kernel 1: build U into __device__ scratch (only ptile<=qtile blocks).
// Kernel 2: fused basis + quadratic form. Warps free-run over a statically
//   balanced triangular schedule: the 72 half-chunks (32p x 64q) of the
//   triangle are split 9-per-warp (<=3 segments each); each segment gets its
//   own accumulate + epilogue + atomicAdd (legal because rho is linear in
//   the partial acc). All warps do exactly 288 p-rows -> both warps per
//   SMSP stay active, full latency hiding, no mainloop barriers.

#define N_MOL   16
#define MS      4096
#define NA      32
#define NP      512
#define M_TILE  64
#define THREADS 256
#define DV_LD   65

// smem (floats): sB 32768 | scratch dvT 96*65 + r2 32*64 | params 1536 | rho 64
#define SCRATCH_FLOATS (96 * DV_LD + 32 * 64)
#define SMEM_FLOATS (32768 + SCRATCH_FLOATS + 512 + 512 + 512 + 64)
#define SMEM_BYTES  (SMEM_FLOATS * 4)

// symmetrized, block-weighted density matrix (zero-init; P>Q blocks never
// written and never consumed -> deterministic)
__device__ float g_U[(size_t)N_MOL * NP * NP];

__constant__ int c_pw[20 * 3] = {
    0,0,0,
    1,0,0, 0,1,0, 0,0,1,
    2,0,0, 0,2,0, 0,0,2, 1,1,0, 1,0,1, 0,1,1,
    3,0,0, 0,3,0, 0,0,3, 2,1,0, 2,0,1, 0,2,1,
    1,2,0, 1,0,2, 0,1,2, 1,1,1
};

// per-warp triangular schedule: 3 segments x (qtile, half_start, half_end);
// qtile = -1 terminates. halves are 32 p-rows. 9 halves per warp, exact cover.
__constant__ int c_sched[8][3][3] = {
    { { 7, 0, 9 },  { -1, 0, 0 }, { -1, 0, 0 } },
    { { 7, 9, 16 }, { 6, 0, 2 },  { -1, 0, 0 } },
    { { 6, 2, 11 }, { -1, 0, 0 }, { -1, 0, 0 } },
    { { 6, 11, 14 },{ 5, 0, 6 },  { -1, 0, 0 } },
    { { 5, 6, 12 }, { 4, 0, 3 },  { -1, 0, 0 } },
    { { 4, 3, 10 }, { 3, 0, 2 },  { -1, 0, 0 } },
    { { 3, 2, 8 },  { 2, 0, 3 },  { -1, 0, 0 } },
    { { 2, 3, 6 },  { 1, 0, 4 },  { 0, 0, 2 } },
};

__device__ __forceinline__ float ipow_small(float x, int e) {
    // x^e for e in {0,1,2,3}; pow(x,0)==1 for any x (matches XLA semantics)
    float r = (e > 0 ? x : 1.0f);
    r *= (e > 1 ? x : 1.0f);
    r *= (e > 2 ? x : 1.0f);
    return r;
}

// ---- kernel 1: U = (D + D^T) with block-triangular weights ----
__global__ void build_U_kernel(const float* __restrict__ dm) {
    __shared__ float tA[32][33];
    __shared__ float tB[32][33];
    const int n  = blockIdx.z;
    const int bp = blockIdx.y * 32;
    const int bq = blockIdx.x * 32;
    const int ptile = bp >> 6, qtile = bq >> 6;
    if (ptile > qtile) return;                 // unused region stays zero

    const float* D = dm + (size_t)n * NP * NP;
    const int tx = threadIdx.x, ty0 = threadIdx.y;   // block (32, 8)
    for (int r = ty0; r < 32; r += 8) {
        tA[r][tx] = D[(size_t)(bp + r) * NP + bq + tx];
        tB[r][tx] = D[(size_t)(bq + r) * NP + bp + tx];
    }
    __syncthreads();

    const float w = (ptile == qtile) ? 0.5f : 1.0f;
    float* U = g_U + (size_t)n * NP * NP;
    for (int r = ty0; r < 32; r += 8)
        U[(size_t)(bp + r) * NP + bq + tx] = (tA[r][tx] + tB[tx][r]) * w;
}

// ---- kernel 2: fused basis + balanced free-running quadratic form ----
__global__ __launch_bounds__(THREADS, 1)
void wfn_density_kernel(const float* __restrict__ dv,
                        const int*   __restrict__ centers,
                        const float* __restrict__ exps,
                        const int*   __restrict__ syms,
                        float*       __restrict__ out) {
    extern __shared__ float smem[];
    float* sB   = smem;                          // 32768 floats
    float* dvT  = smem + 32768;                  // [96][DV_LD]
    float* r2s  = dvT + 96 * DV_LD;              // [32][64]
    float* sExp = smem + 32768 + SCRATCH_FLOATS; // 512
    int*   sCen = (int*)(sExp + 512);
    int*   sSym = sCen + 512;
    float* rhoS = (float*)(sSym + 512);          // 64

    const int tid = threadIdx.x;
    const int n   = blockIdx.y;
    const int m0  = blockIdx.x * M_TILE;

    // ---- per-primitive params ----
    for (int i = tid; i < NP; i += THREADS) {
        sExp[i] = exps[n * NP + i];
        sCen[i] = centers[n * NP + i];
        sSym[i] = syms[n * NP + i];
    }
    if (tid < M_TILE) rhoS[tid] = 0.0f;

    // ---- dv tile, transposed ----
    const float* dvsrc = dv + ((size_t)n * MS + m0) * (NA * 3);
    for (int L = tid; L < M_TILE * NA * 3; L += THREADS) {
        int mm = L / (NA * 3);
        int t  = L % (NA * 3);
        dvT[t * DV_LD + mm] = dvsrc[L];
    }
    __syncthreads();

    // ---- r2 per (atom, sample) ----
    for (int idx = tid; idx < NA * M_TILE; idx += THREADS) {
        int a = idx >> 6, mm = idx & 63;
        float x = dvT[(a * 3 + 0) * DV_LD + mm];
        float y = dvT[(a * 3 + 1) * DV_LD + mm];
        float z = dvT[(a * 3 + 2) * DV_LD + mm];
        r2s[a * 64 + mm] = x * x + y * y + z * z;
    }
    __syncthreads();

    // ---- basis tile sB[p][mm] ----
    for (int e = tid; e < NP * M_TILE; e += THREADS) {
        int p  = e >> 6;
        int mm = e & 63;
        int c  = sCen[p];
        int cc = max(c, 0);
        float alpha = sExp[p];
        int s  = sSym[p];
        int px = c_pw[s * 3 + 0], py = c_pw[s * 3 + 1], pz = c_pw[s * 3 + 2];
        float x  = dvT[(cc * 3 + 0) * DV_LD + mm];
        float y  = dvT[(cc * 3 + 1) * DV_LD + mm];
        float z  = dvT[(cc * 3 + 2) * DV_LD + mm];
        float r2 = r2s[cc * 64 + mm];
        float ang = ipow_small(x, px) * ipow_small(y, py) * ipow_small(z, pz);
        float b = ang * __expf(-alpha * r2);
        sB[p * M_TILE + mm] = (c >= 0) ? b : 0.0f;
    }
    __syncthreads();   // sB complete; warps free-run from here

    // ---- phase 2: balanced triangular segments ----
    const float* Ug = g_U + (size_t)n * NP * NP;
    const int warp = tid >> 5;
    const int tm   = tid & 3;          // m-group: m = tm*16 + i, i in 0..15
    const int tqin = (tid >> 2) & 7;   // q-group within warp, j in 0..7

    for (int s = 0; s < 3; ++s) {
        const int qt = c_sched[warp][s][0];
        if (qt < 0) break;
        const int p0 = c_sched[warp][s][1] * 32;
        const int p1 = c_sched[warp][s][2] * 32;
        const int q0 = qt * 64 + tqin * 8;

        float acc[16][8];
        #pragma unroll
        for (int i = 0; i < 16; ++i)
            #pragma unroll
            for (int j = 0; j < 8; ++j) acc[i][j] = 0.0f;

        const float4* Uq = (const float4*)(Ug + q0);  // row p: Uq[p*128], +1
        // distance-2 software pipeline over p (pairs; prefetch next pair)
        float4 uA0 = __ldg(&Uq[(size_t)p0 * 128]);
        float4 uA1 = __ldg(&Uq[(size_t)p0 * 128 + 1]);
        float4 uB0 = __ldg(&Uq[(size_t)(p0 + 1) * 128]);
        float4 uB1 = __ldg(&Uq[(size_t)(p0 + 1) * 128 + 1]);

        for (int p = p0; p < p1; p += 2) {
            float4 c0 = uA0, c1 = uA1, e0 = uB0, e1 = uB1;
            if (p + 3 < p1) {
                uA0 = __ldg(&Uq[(size_t)(p + 2) * 128]);
                uA1 = __ldg(&Uq[(size_t)(p + 2) * 128 + 1]);
                uB0 = __ldg(&Uq[(size_t)(p + 3) * 128]);
                uB1 = __ldg(&Uq[(size_t)(p + 3) * 128 + 1]);
            }
            // row p
            {
                const float* brow = &sB[p * M_TILE + tm * 16];
                float4 b0 = *(const float4*)&brow[0];
                float4 b1 = *(const float4*)&brow[4];
                float4 b2 = *(const float4*)&brow[8];
                float4 b3 = *(const float4*)&brow[12];
                float bb[16] = {b0.x, b0.y, b0.z, b0.w, b1.x, b1.y, b1.z, b1.w,
                                b2.x, b2.y, b2.z, b2.w, b3.x, b3.y, b3.z, b3.w};
                float dd[8]  = {c0.x, c0.y, c0.z, c0.w, c1.x, c1.y, c1.z, c1.w};
                #pragma unroll
                for (int i = 0; i < 16; ++i)
                    #pragma unroll
                    for (int j = 0; j < 8; ++j)
                        acc[i][j] = fmaf(bb[i], dd[j], acc[i][j]);
            }
            // row p + 1
            {
                const float* brow = &sB[(p + 1) * M_TILE + tm * 16];
                float4 b0 = *(const float4*)&brow[0];
                float4 b1 = *(const float4*)&brow[4];
                float4 b2 = *(const float4*)&brow[8];
                float4 b3 = *(const float4*)&brow[12];
                float bb[16] = {b0.x, b0.y, b0.z, b0.w, b1.x, b1.y, b1.z, b1.w,
                                b2.x, b2.y, b2.z, b2.w, b3.x, b3.y, b3.z, b3.w};
                float dd[8]  = {e0.x, e0.y, e0.z, e0.w, e1.x, e1.y, e1.z, e1.w};
                #pragma unroll
                for (int i = 0; i < 16; ++i)
                    #pragma unroll
                    for (int j = 0; j < 8; ++j)
                        acc[i][j] = fmaf(bb[i], dd[j], acc[i][j]);
            }
        }

        // segment epilogue: part[i] = sum_j acc[i][j] * B[q_j, m_i]
        float part[16];
        #pragma unroll
        for (int i = 0; i < 16; ++i) part[i] = 0.0f;
        #pragma unroll
        for (int j = 0; j < 8; ++j) {
            const float* col = &sB[(q0 + j) * M_TILE + tm * 16];
            float4 c0 = *(const float4*)&col[0];
            float4 c1 = *(const float4*)&col[4];
            float4 c2 = *(const float4*)&col[8];
            float4 c3 = *(const float4*)&col[12];
            float cc[16] = {c0.x, c0.y, c0.z, c0.w, c1.x, c1.y, c1.z, c1.w,
                            c2.x, c2.y, c2.z, c2.w, c3.x, c3.y, c3.z, c3.w};
            #pragma unroll
            for (int i = 0; i < 16; ++i)
                part[i] = fmaf(acc[i][j], cc[i], part[i]);
        }
        // reduce across the 8 lanes sharing tm (lane bits 2,3,4)
        #pragma unroll
        for (int i = 0; i < 16; ++i) {
            part[i] += __shfl_xor_sync(0xFFFFFFFFu, part[i], 4);
            part[i] += __shfl_xor_sync(0xFFFFFFFFu, part[i], 8);
            part[i] += __shfl_xor_sync(0xFFFFFFFFu, part[i], 16);
        }
        if (tqin == 0) {
            #pragma unroll
            for (int i = 0; i < 16; ++i)
                atomicAdd(&rhoS[tm * 16 + i], part[i]);
        }
    }

    __syncthreads();
    if (tid < M_TILE)
        out[(size_t)n * MS + m0 + tid] = rhoS[tid];
}

extern "C" void kernel_launch(void* const* d_in, const int* in_sizes, int n_in,
                              void* d_out, int out_size) {
    const float* dv      = (const float*)d_in[0];
    const int*   centers = (const int*)  d_in[1];
    const float* exps    = (const float*)d_in[2];
    const int*   syms    = (const int*)  d_in[3];
    const float* dm      = (const float*)d_in[4];
    float* out = (float*)d_out;

    cudaFuncSetAttribute(wfn_density_kernel,
                         cudaFuncAttributeMaxDynamicSharedMemorySize, SMEM_BYTES);

    // 1) symmetrize + weight the density matrix
    dim3 ug(NP / 32, NP / 32, N_MOL);
    build_U_kernel<<<ug, dim3(32, 8)>>>(dm);

    // 2) fused density evaluation
    dim3 grid(MS / M_TILE, N_MOL);
    wfn_density_kernel<<<grid, THREADS, SMEM_BYTES>>>(dv, centers, exps, syms, out);
}